// round 5
// baseline (speedup 1.0000x reference)
#include <cuda_runtime.h>
#include <cuda_bf16.h>
#include <math.h>
#include <cstdint>

// Problem constants
constexpr int B_  = 2;
constexpr int S_  = 2048;
constexpr int D_  = 1024;
constexpr int H_  = 16;
constexpr int HD_ = 64;
constexpr int M_  = B_ * S_;       // 4096

// Scratch (device globals — allocation-free per harness rules)
__device__ __nv_bfloat16 g_xh[M_ * D_];         // GEMM A operand (x, then attn-out), hi
__device__ __nv_bfloat16 g_xl[M_ * D_];         // lo
__device__ __nv_bfloat16 g_wh[4 * D_ * D_];     // Wq|Wk|Wv|Wo stacked, hi
__device__ __nv_bfloat16 g_wl[4 * D_ * D_];     // lo
__device__ __nv_bfloat16 g_Qh[B_ * H_ * S_ * HD_];   // [b,h,s,hd]
__device__ __nv_bfloat16 g_Ql[B_ * H_ * S_ * HD_];
__device__ __nv_bfloat16 g_Kh[B_ * H_ * S_ * HD_];
__device__ __nv_bfloat16 g_Kl[B_ * H_ * S_ * HD_];
__device__ __nv_bfloat16 g_Vth[B_ * H_ * HD_ * S_];  // [b,h,hd,s] transposed
__device__ __nv_bfloat16 g_Vtl[B_ * H_ * HD_ * S_];

// ---------------------------------------------------------------------------
// Helpers: mma.sync / ldmatrix / cp.async (valid on compute_103 PTX)
// ---------------------------------------------------------------------------
__device__ __forceinline__ uint32_t smem_to_u32(const void* p) {
    uint32_t a;
    asm("{ .reg .u64 t; cvta.to.shared.u64 t, %1; cvt.u32.u64 %0, t; }"
        : "=r"(a) : "l"(p));
    return a;
}

__device__ __forceinline__ void ldsm_x4(uint32_t* r, uint32_t addr) {
    asm volatile("ldmatrix.sync.aligned.m8n8.x4.shared.b16 {%0,%1,%2,%3}, [%4];"
        : "=r"(r[0]), "=r"(r[1]), "=r"(r[2]), "=r"(r[3]) : "r"(addr));
}

__device__ __forceinline__ void mma_bf16(float* c, const uint32_t* a, const uint32_t* b) {
    asm volatile(
        "mma.sync.aligned.m16n8k16.row.col.f32.bf16.bf16.f32 "
        "{%0,%1,%2,%3}, {%4,%5,%6,%7}, {%8,%9}, {%0,%1,%2,%3};"
        : "+f"(c[0]), "+f"(c[1]), "+f"(c[2]), "+f"(c[3])
        : "r"(a[0]), "r"(a[1]), "r"(a[2]), "r"(a[3]),
          "r"(b[0]), "r"(b[1]));
}

#define CP_ASYNC16(dst, src) \
    asm volatile("cp.async.cg.shared.global [%0], [%1], 16;" \
        :: "r"(dst), "l"(src) : "memory")
#define CP_COMMIT() asm volatile("cp.async.commit_group;" ::: "memory")
#define CP_WAIT1()  asm volatile("cp.async.wait_group 1;" ::: "memory")

// FMA-pipe exp2 (avoids the MUFU ceiling). x <= 0 expected.
__device__ __forceinline__ float exp2p(float x) {
    x = fmaxf(x, -28.0f);
    float n = floorf(x);
    float f = x - n;
    float p = 1.54035304e-4f;
    p = fmaf(p, f, 1.33335581e-3f);
    p = fmaf(p, f, 9.61812911e-3f);
    p = fmaf(p, f, 5.55041087e-2f);
    p = fmaf(p, f, 2.40226507e-1f);
    p = fmaf(p, f, 6.93147181e-1f);
    p = fmaf(p, f, 1.0f);
    return __int_as_float(__float_as_int(p) + (((int)n) << 23));
}

__device__ __forceinline__ void split_bf16(float v, __nv_bfloat16& h, __nv_bfloat16& l) {
    h = __float2bfloat16(v);
    l = __float2bfloat16(v - __bfloat162float(h));
}

// ---------------------------------------------------------------------------
// One-shot converter: x -> g_xh/g_xl ; Wq,Wk,Wv,Wo -> g_wh/g_wl (stacked rows)
// Blocks [0,4096): x (4M elems). Blocks [4096,8192): weights (4 x 1M elems).
// ---------------------------------------------------------------------------
__global__ void __launch_bounds__(256)
convert_all_kernel(const float* __restrict__ x,
                   const float* __restrict__ Wq, const float* __restrict__ Wk,
                   const float* __restrict__ Wv, const float* __restrict__ Wo)
{
    const int tid = threadIdx.x;
    const int blk = blockIdx.x;

    const float* src;
    __nv_bfloat16 *hi, *lo;
    size_t sbase, dbase;
    if (blk < 4096) {
        src = x; hi = g_xh; lo = g_xl;
        sbase = (size_t)blk * 1024; dbase = sbase;
    } else {
        const int t = blk - 4096;
        const int w = t >> 10;
        const int lb = t & 1023;
        src = (w == 0) ? Wq : (w == 1) ? Wk : (w == 2) ? Wv : Wo;
        hi = g_wh; lo = g_wl;
        sbase = (size_t)lb * 1024;
        dbase = (size_t)w * (D_ * D_) + sbase;
    }

    const int i = tid * 4;
    float4 v = *(const float4*)(src + sbase + i);
    float f[4] = {v.x, v.y, v.z, v.w};
    __nv_bfloat16 h[4], l[4];
#pragma unroll
    for (int k = 0; k < 4; k++) split_bf16(f[k], h[k], l[k]);
    __nv_bfloat162* ph = (__nv_bfloat162*)(hi + dbase + i);
    __nv_bfloat162* pl = (__nv_bfloat162*)(lo + dbase + i);
    ph[0] = __halves2bfloat162(h[0], h[1]);
    ph[1] = __halves2bfloat162(h[2], h[3]);
    pl[0] = __halves2bfloat162(l[0], l[1]);
    pl[1] = __halves2bfloat162(l[2], l[3]);
}

// ---------------------------------------------------------------------------
// bf16x3 GEMM via mma.sync: C[M,N] = A @ W^T + bias.
// dst == nullptr: merged QKV (N = 3072, sel = bn>>10 picks Q/K/V epilogue,
//                 bias from b0/b1/b2). wrow0 = 0.
// dst != nullptr: O-projection (N = 1024, wrow0 = 3072, fp32 row-major dst).
// CTA 128x128, BK=32, 8 warps, 3-stage cp.async pipeline.
// MMA issue is term-major (hh sweep, hl sweep, lh sweep) -> same-acc gap = 16.
// ---------------------------------------------------------------------------
constexpr int KPAD    = 40;
constexpr int TILE_B  = 128 * KPAD * 2;        // 10240 B
constexpr int STAGE_B = 4 * TILE_B;            // 40960 B
constexpr int GEMM_SMEM = 3 * STAGE_B;         // 122880 B

__global__ void __launch_bounds__(256)
gemm_mma_kernel(const float* __restrict__ b0,
                const float* __restrict__ b1,
                const float* __restrict__ b2,
                float* __restrict__ dst,
                int wrow0)
{
    extern __shared__ __align__(1024) char smem[];
    const uint32_t sb = smem_to_u32(smem);
    const int tid = threadIdx.x;
    const int wid = tid >> 5;
    const int lid = tid & 31;
    const int wm  = wid & 3;
    const int wn  = wid >> 2;
    const int bm  = blockIdx.y * 128;
    const int bn  = blockIdx.x * 128;
    const int sel = bn >> 10;                  // 0/1/2 for QKV; 0 for O

    const float* bias = dst ? b0 : (sel == 0 ? b0 : sel == 1 ? b1 : b2);

    const int r4 = tid >> 2;
    const int s4 = tid & 3;

    auto issue_stage = [&](int st) {
        const int k0 = st * 32;
        const uint32_t sbase = sb + (st % 3) * STAGE_B;
#pragma unroll
        for (int j = 0; j < 2; j++) {
            const int r = r4 + j * 64;
            const uint32_t doff = (uint32_t)(r * KPAD + s4 * 8) * 2;
            const size_t aoff = (size_t)(bm + r) * D_ + k0 + s4 * 8;
            const size_t boff = (size_t)(wrow0 + bn + r) * D_ + k0 + s4 * 8;
            CP_ASYNC16(sbase + 0 * TILE_B + doff, g_xh + aoff);
            CP_ASYNC16(sbase + 1 * TILE_B + doff, g_xl + aoff);
            CP_ASYNC16(sbase + 2 * TILE_B + doff, g_wh + boff);
            CP_ASYNC16(sbase + 3 * TILE_B + doff, g_wl + boff);
        }
    };

    float c[2][8][4];
#pragma unroll
    for (int i = 0; i < 2; i++)
#pragma unroll
        for (int j = 0; j < 8; j++)
#pragma unroll
            for (int k = 0; k < 4; k++) c[i][j][k] = 0.f;

    const uint32_t a_r  = lid & 15;
    const uint32_t a_c8 = (lid >> 4) * 8;
    const uint32_t b_r  = ((lid >> 4) * 8) + (lid & 7);
    const uint32_t b_c8 = ((lid >> 3) & 1) * 8;

    issue_stage(0); CP_COMMIT();
    issue_stage(1); CP_COMMIT();

    const int NCH = D_ / 32;
    for (int ch = 0; ch < NCH; ch++) {
        CP_WAIT1();
        __syncthreads();
        if (ch + 2 < NCH) issue_stage(ch + 2);
        CP_COMMIT();

        const uint32_t sA_h = sb + (ch % 3) * STAGE_B;
        const uint32_t sA_l = sA_h + TILE_B;
        const uint32_t sB_h = sA_h + 2 * TILE_B;
        const uint32_t sB_l = sA_h + 3 * TILE_B;

#pragma unroll
        for (int kk = 0; kk < 2; kk++) {
            uint32_t ah[2][4], al[2][4];
#pragma unroll
            for (int mt = 0; mt < 2; mt++) {
                const uint32_t aoff =
                    ((wm * 32 + mt * 16 + a_r) * KPAD + kk * 16 + a_c8) * 2;
                ldsm_x4(ah[mt], sA_h + aoff);
                ldsm_x4(al[mt], sA_l + aoff);
            }
            uint32_t bh[4][4], bl[4][4];
#pragma unroll
            for (int np = 0; np < 4; np++) {
                const uint32_t boff =
                    ((wn * 64 + np * 16 + b_r) * KPAD + kk * 16 + b_c8) * 2;
                ldsm_x4(bh[np], sB_h + boff);
                ldsm_x4(bl[np], sB_l + boff);
            }
            // term-major: same-accumulator reuse gap = 16 MMAs
#pragma unroll
            for (int mt = 0; mt < 2; mt++)
#pragma unroll
                for (int np = 0; np < 4; np++) {
                    mma_bf16(c[mt][2*np],   ah[mt], bh[np]);
                    mma_bf16(c[mt][2*np+1], ah[mt], bh[np] + 2);
                }
#pragma unroll
            for (int mt = 0; mt < 2; mt++)
#pragma unroll
                for (int np = 0; np < 4; np++) {
                    mma_bf16(c[mt][2*np],   ah[mt], bl[np]);
                    mma_bf16(c[mt][2*np+1], ah[mt], bl[np] + 2);
                }
#pragma unroll
            for (int mt = 0; mt < 2; mt++)
#pragma unroll
                for (int np = 0; np < 4; np++) {
                    mma_bf16(c[mt][2*np],   al[mt], bh[np]);
                    mma_bf16(c[mt][2*np+1], al[mt], bh[np] + 2);
                }
        }
    }

    // ---- epilogue ------------------------------------------------------
#pragma unroll
    for (int mt = 0; mt < 2; mt++) {
#pragma unroll
        for (int nt = 0; nt < 8; nt++) {
            const int row0 = bm + wm * 32 + mt * 16 + (lid >> 2);
            const int row1 = row0 + 8;
            const int col  = bn + wn * 64 + nt * 8 + (lid & 3) * 2;
            const int colw = col & 1023;
            const float bx = __ldg(bias + colw);
            const float by = __ldg(bias + colw + 1);
            float v0 = c[mt][nt][0] + bx, v1 = c[mt][nt][1] + by;
            float v2 = c[mt][nt][2] + bx, v3 = c[mt][nt][3] + by;

            if (dst) {
                *(float2*)(dst + (size_t)row0 * D_ + col) = make_float2(v0, v1);
                *(float2*)(dst + (size_t)row1 * D_ + col) = make_float2(v2, v3);
            } else {
                const int h  = colw >> 6;
                const int hd = colw & 63;
                const int bb0 = row0 >> 11, ss0 = row0 & (S_ - 1);
                const int bb1 = row1 >> 11, ss1 = row1 & (S_ - 1);
                __nv_bfloat16 h0,l0,h1,l1,h2,l2,h3,l3;
                split_bf16(v0,h0,l0); split_bf16(v1,h1,l1);
                split_bf16(v2,h2,l2); split_bf16(v3,h3,l3);
                if (sel == 2) {
                    // V transposed: [b,h,hd,s]
                    size_t base0 = (((size_t)(bb0 * H_ + h) * HD_) + hd) * S_;
                    size_t base1 = (((size_t)(bb1 * H_ + h) * HD_) + hd) * S_;
                    g_Vth[base0 + ss0]      = h0; g_Vtl[base0 + ss0]      = l0;
                    g_Vth[base0 + S_ + ss0] = h1; g_Vtl[base0 + S_ + ss0] = l1;
                    g_Vth[base1 + ss1]      = h2; g_Vtl[base1 + ss1]      = l2;
                    g_Vth[base1 + S_ + ss1] = h3; g_Vtl[base1 + S_ + ss1] = l3;
                } else {
                    __nv_bfloat16* dh = (sel == 0) ? g_Qh : g_Kh;
                    __nv_bfloat16* dl = (sel == 0) ? g_Ql : g_Kl;
                    size_t i0 = (((size_t)(bb0 * H_ + h) * S_) + ss0) * HD_ + hd;
                    size_t i1 = (((size_t)(bb1 * H_ + h) * S_) + ss1) * HD_ + hd;
                    *(__nv_bfloat162*)(dh + i0) = __halves2bfloat162(h0, h1);
                    *(__nv_bfloat162*)(dl + i0) = __halves2bfloat162(l0, l1);
                    *(__nv_bfloat162*)(dh + i1) = __halves2bfloat162(h2, h3);
                    *(__nv_bfloat162*)(dl + i1) = __halves2bfloat162(l2, l3);
                }
            }
        }
    }
}

// ---------------------------------------------------------------------------
// Flash attention via mma.sync bf16x3 + FMA-pipe exp2 (term-major MMA issue).
// Grid (S/128, B*H), 256 threads (8 warps x 16 query rows). Bc = 64.
// ---------------------------------------------------------------------------
constexpr int FKP = 72;
constexpr int FQ_B    = 128 * FKP * 2;          // 18432 B
constexpr int FKV_B   = 64 * FKP * 2;           // 9216 B
constexpr int FSTAGE_B = 4 * FKV_B;             // 36864 B
constexpr int FLASH_SMEM = 2 * FQ_B + 2 * FSTAGE_B;   // 110592 B
constexpr float SCL2 = 0.18033688f;             // 0.125 * log2(e)

__global__ void __launch_bounds__(256)
flash_mma_kernel()
{
    extern __shared__ __align__(1024) char fsm[];
    const uint32_t sb = smem_to_u32(fsm);
    const int tid = threadIdx.x;
    const int wid = tid >> 5;
    const int lid = tid & 31;
    const int bh  = blockIdx.y;
    const int q0  = blockIdx.x * 128;

    const size_t qk_base = (size_t)bh * S_ * HD_;
    const size_t vt_base = (size_t)bh * HD_ * S_;
    const __nv_bfloat16* Qh = g_Qh + qk_base;
    const __nv_bfloat16* Ql = g_Ql + qk_base;
    const __nv_bfloat16* Kh = g_Kh + qk_base;
    const __nv_bfloat16* Kl = g_Kl + qk_base;
    const __nv_bfloat16* Vh = g_Vth + vt_base;
    const __nv_bfloat16* Vl = g_Vtl + vt_base;

    const uint32_t oQh = sb;
    const uint32_t oQl = sb + FQ_B;

    auto issue_kv = [&](int t) {
        const int k0 = t * 64;
        const uint32_t st = sb + 2 * FQ_B + (t & 1) * FSTAGE_B;
        const int row = tid >> 2;
        const int c0  = (tid & 3) * 16;
        const uint32_t doff = (uint32_t)(row * FKP + c0) * 2;
        const size_t koff = (size_t)(k0 + row) * HD_ + c0;
        const size_t voff = (size_t)row * S_ + k0 + c0;
#pragma unroll
        for (int j = 0; j < 2; j++) {
            CP_ASYNC16(st + 0 * FKV_B + doff + j * 16, Kh + koff + j * 8);
            CP_ASYNC16(st + 1 * FKV_B + doff + j * 16, Kl + koff + j * 8);
            CP_ASYNC16(st + 2 * FKV_B + doff + j * 16, Vh + voff + j * 8);
            CP_ASYNC16(st + 3 * FKV_B + doff + j * 16, Vl + voff + j * 8);
        }
    };

    {
        const int row = tid >> 1;
        const int c0  = (tid & 1) * 32;
        const uint32_t doff = (uint32_t)(row * FKP + c0) * 2;
        const size_t off = (size_t)(q0 + row) * HD_ + c0;
#pragma unroll
        for (int j = 0; j < 4; j++) {
            CP_ASYNC16(oQh + doff + j * 16, Qh + off + j * 8);
            CP_ASYNC16(oQl + doff + j * 16, Ql + off + j * 8);
        }
    }
    issue_kv(0); CP_COMMIT();
    issue_kv(1); CP_COMMIT();

    const uint32_t a_r  = lid & 15;
    const uint32_t a_c8 = (lid >> 4) * 8;
    const uint32_t b_r  = ((lid >> 4) * 8) + (lid & 7);
    const uint32_t b_c8 = ((lid >> 3) & 1) * 8;

    CP_WAIT1();
    __syncthreads();

    uint32_t qfh[4][4], qfl[4][4];
#pragma unroll
    for (int kk = 0; kk < 4; kk++) {
        const uint32_t aoff = ((wid * 16 + a_r) * FKP + kk * 16 + a_c8) * 2;
        ldsm_x4(qfh[kk], oQh + aoff);
        ldsm_x4(qfl[kk], oQl + aoff);
    }

    float o[8][4];
#pragma unroll
    for (int i = 0; i < 8; i++)
#pragma unroll
        for (int j = 0; j < 4; j++) o[i][j] = 0.f;
    float m0 = -1e30f, m1 = -1e30f, l0 = 0.f, l1 = 0.f;

    const int NKV = S_ / 64;
    for (int t = 0; t < NKV; t++) {
        if (t > 0) { CP_WAIT1(); __syncthreads(); }

        const uint32_t st  = sb + 2 * FQ_B + (t & 1) * FSTAGE_B;
        const uint32_t sKh = st, sKl = st + FKV_B;
        const uint32_t sVh = st + 2 * FKV_B, sVl = st + 3 * FKV_B;

        // ---- S = Q K^T (term-major) --------------------------------------
        float c[8][4];
#pragma unroll
        for (int i = 0; i < 8; i++)
#pragma unroll
            for (int j = 0; j < 4; j++) c[i][j] = 0.f;

#pragma unroll
        for (int kk = 0; kk < 4; kk++) {
            uint32_t kfh[4][4], kfl[4][4];
#pragma unroll
            for (int np = 0; np < 4; np++) {
                const uint32_t boff = ((np * 16 + b_r) * FKP + kk * 16 + b_c8) * 2;
                ldsm_x4(kfh[np], sKh + boff);
                ldsm_x4(kfl[np], sKl + boff);
            }
#pragma unroll
            for (int np = 0; np < 4; np++) {
                mma_bf16(c[2*np],   qfh[kk], kfh[np]);
                mma_bf16(c[2*np+1], qfh[kk], kfh[np] + 2);
            }
#pragma unroll
            for (int np = 0; np < 4; np++) {
                mma_bf16(c[2*np],   qfh[kk], kfl[np]);
                mma_bf16(c[2*np+1], qfh[kk], kfl[np] + 2);
            }
#pragma unroll
            for (int np = 0; np < 4; np++) {
                mma_bf16(c[2*np],   qfl[kk], kfh[np]);
                mma_bf16(c[2*np+1], qfl[kk], kfh[np] + 2);
            }
        }

        // ---- online softmax ----------------------------------------------
        float mx0 = -1e30f, mx1 = -1e30f;
#pragma unroll
        for (int nt = 0; nt < 8; nt++) {
            mx0 = fmaxf(mx0, fmaxf(c[nt][0], c[nt][1]));
            mx1 = fmaxf(mx1, fmaxf(c[nt][2], c[nt][3]));
        }
        mx0 = fmaxf(mx0, __shfl_xor_sync(0xffffffffu, mx0, 1));
        mx0 = fmaxf(mx0, __shfl_xor_sync(0xffffffffu, mx0, 2));
        mx1 = fmaxf(mx1, __shfl_xor_sync(0xffffffffu, mx1, 1));
        mx1 = fmaxf(mx1, __shfl_xor_sync(0xffffffffu, mx1, 2));

        const float mn0 = fmaxf(m0, mx0), mn1 = fmaxf(m1, mx1);
        const float al0 = exp2p((m0 - mn0) * SCL2);
        const float al1 = exp2p((m1 - mn1) * SCL2);
        m0 = mn0; m1 = mn1;
        const float mb0 = mn0 * SCL2, mb1 = mn1 * SCL2;

        float s0 = 0.f, s1 = 0.f;
#pragma unroll
        for (int nt = 0; nt < 8; nt++) {
            c[nt][0] = exp2p(fmaf(c[nt][0], SCL2, -mb0));
            c[nt][1] = exp2p(fmaf(c[nt][1], SCL2, -mb0));
            c[nt][2] = exp2p(fmaf(c[nt][2], SCL2, -mb1));
            c[nt][3] = exp2p(fmaf(c[nt][3], SCL2, -mb1));
            s0 += c[nt][0] + c[nt][1];
            s1 += c[nt][2] + c[nt][3];
        }
        s0 += __shfl_xor_sync(0xffffffffu, s0, 1);
        s0 += __shfl_xor_sync(0xffffffffu, s0, 2);
        s1 += __shfl_xor_sync(0xffffffffu, s1, 1);
        s1 += __shfl_xor_sync(0xffffffffu, s1, 2);
        l0 = l0 * al0 + s0;
        l1 = l1 * al1 + s1;

#pragma unroll
        for (int nt = 0; nt < 8; nt++) {
            o[nt][0] *= al0; o[nt][1] *= al0;
            o[nt][2] *= al1; o[nt][3] *= al1;
        }

        // ---- pack P into A-fragments (hi/lo) ------------------------------
        uint32_t pfh[4][4], pfl[4][4];
#pragma unroll
        for (int kk2 = 0; kk2 < 4; kk2++) {
            const int n0 = 2 * kk2, n1 = 2 * kk2 + 1;
            float ph[8], pl[8];
            float src[8] = {c[n0][0], c[n0][1], c[n0][2], c[n0][3],
                            c[n1][0], c[n1][1], c[n1][2], c[n1][3]};
#pragma unroll
            for (int e = 0; e < 8; e++) {
                __nv_bfloat16 hb = __float2bfloat16(src[e]);
                ph[e] = __bfloat162float(hb);
                pl[e] = src[e] - ph[e];
            }
            __nv_bfloat162 t0, t1;
#pragma unroll
            for (int q = 0; q < 4; q++) {
                t0 = __floats2bfloat162_rn(ph[2*q], ph[2*q+1]);
                t1 = __floats2bfloat162_rn(pl[2*q], pl[2*q+1]);
                pfh[kk2][q] = *(uint32_t*)&t0;
                pfl[kk2][q] = *(uint32_t*)&t1;
            }
        }

        // ---- O += P V (term-major) ----------------------------------------
#pragma unroll
        for (int kk2 = 0; kk2 < 4; kk2++) {
            uint32_t vfh[4][4], vfl[4][4];
#pragma unroll
            for (int np = 0; np < 4; np++) {
                const uint32_t boff = ((np * 16 + b_r) * FKP + kk2 * 16 + b_c8) * 2;
                ldsm_x4(vfh[np], sVh + boff);
                ldsm_x4(vfl[np], sVl + boff);
            }
#pragma unroll
            for (int np = 0; np < 4; np++) {
                mma_bf16(o[2*np],   pfh[kk2], vfh[np]);
                mma_bf16(o[2*np+1], pfh[kk2], vfh[np] + 2);
            }
#pragma unroll
            for (int np = 0; np < 4; np++) {
                mma_bf16(o[2*np],   pfh[kk2], vfl[np]);
                mma_bf16(o[2*np+1], pfh[kk2], vfl[np] + 2);
            }
#pragma unroll
            for (int np = 0; np < 4; np++) {
                mma_bf16(o[2*np],   pfl[kk2], vfh[np]);
                mma_bf16(o[2*np+1], pfl[kk2], vfh[np] + 2);
            }
        }

        __syncthreads();
        if (t + 2 < NKV) issue_kv(t + 2);
        CP_COMMIT();
    }

    // ---- epilogue: normalize, write bf16 hi/lo into final-GEMM staging ----
    const int b = bh >> 4;
    const int h = bh & 15;
    const float li0 = 1.f / l0;
    const float li1 = 1.f / l1;
    const int r0 = q0 + wid * 16 + (lid >> 2);
    const int r1 = r0 + 8;
    const size_t g0 = ((size_t)(b * S_ + r0)) * D_ + h * 64;
    const size_t g1 = ((size_t)(b * S_ + r1)) * D_ + h * 64;

#pragma unroll
    for (int nt = 0; nt < 8; nt++) {
        const int col = nt * 8 + (lid & 3) * 2;
        float v0 = o[nt][0] * li0, v1 = o[nt][1] * li0;
        float v2 = o[nt][2] * li1, v3 = o[nt][3] * li1;
        __nv_bfloat16 h0,lo0,h1,lo1,h2,lo2,h3,lo3;
        split_bf16(v0,h0,lo0); split_bf16(v1,h1,lo1);
        split_bf16(v2,h2,lo2); split_bf16(v3,h3,lo3);
        *(__nv_bfloat162*)(g_xh + g0 + col) = __halves2bfloat162(h0, h1);
        *(__nv_bfloat162*)(g_xl + g0 + col) = __halves2bfloat162(lo0, lo1);
        *(__nv_bfloat162*)(g_xh + g1 + col) = __halves2bfloat162(h2, h3);
        *(__nv_bfloat162*)(g_xl + g1 + col) = __halves2bfloat162(lo2, lo3);
    }
}

// ---------------------------------------------------------------------------
// Entry point
// ---------------------------------------------------------------------------
extern "C" void kernel_launch(void* const* d_in, const int* in_sizes, int n_in,
                              void* d_out, int out_size)
{
    const float* x  = (const float*)d_in[0];
    const float* Wq = (const float*)d_in[1];
    const float* bq = (const float*)d_in[2];
    const float* Wk = (const float*)d_in[3];
    const float* bk = (const float*)d_in[4];
    const float* Wv = (const float*)d_in[5];
    const float* bv = (const float*)d_in[6];
    const float* Wo = (const float*)d_in[7];
    const float* bo = (const float*)d_in[8];
    float* out = (float*)d_out;

    cudaFuncSetAttribute(gemm_mma_kernel,
                         cudaFuncAttributeMaxDynamicSharedMemorySize, GEMM_SMEM);
    cudaFuncSetAttribute(flash_mma_kernel,
                         cudaFuncAttributeMaxDynamicSharedMemorySize, FLASH_SMEM);

    // 1) convert x + all 4 weights (bf16 hi/lo) in one launch
    convert_all_kernel<<<8192, 256>>>(x, Wq, Wk, Wv, Wo);

    // 2) merged QKV projection: N = 3072
    gemm_mma_kernel<<<dim3(24, 32), 256, GEMM_SMEM>>>(bq, bk, bv, nullptr, 0);

    // 3) flash attention (writes bf16 hi/lo straight into GEMM A-staging)
    flash_mma_kernel<<<dim3(S_ / 128, B_ * H_), 256, FLASH_SMEM>>>();

    // 4) output projection (weight rows 3072..4095)
    gemm_mma_kernel<<<dim3(8, 32), 256, GEMM_SMEM>>>(bo, bo, bo, out, 3072);
}

// round 6
// speedup vs baseline: 1.1394x; 1.1394x over previous
#include <cuda_runtime.h>
#include <cuda_bf16.h>
#include <math.h>
#include <cstdint>

// Problem constants
constexpr int B_  = 2;
constexpr int S_  = 2048;
constexpr int D_  = 1024;
constexpr int H_  = 16;
constexpr int HD_ = 64;
constexpr int M_  = B_ * S_;       // 4096

// Scratch (device globals — allocation-free per harness rules)
__device__ __nv_bfloat16 g_xh[M_ * D_];         // GEMM A operand (x, then attn-out), hi
__device__ __nv_bfloat16 g_xl[M_ * D_];         // lo
__device__ __nv_bfloat16 g_wh[4 * D_ * D_];     // Wq|Wk|Wv|Wo stacked, hi
__device__ __nv_bfloat16 g_wl[4 * D_ * D_];     // lo
__device__ __nv_bfloat16 g_Qh[B_ * H_ * S_ * HD_];   // [b,h,s,hd]
__device__ __nv_bfloat16 g_Ql[B_ * H_ * S_ * HD_];
__device__ __nv_bfloat16 g_Kh[B_ * H_ * S_ * HD_];
__device__ __nv_bfloat16 g_Kl[B_ * H_ * S_ * HD_];
__device__ __nv_bfloat16 g_Vth[B_ * H_ * HD_ * S_];  // [b,h,hd,s] transposed
__device__ __nv_bfloat16 g_Vtl[B_ * H_ * HD_ * S_];

// ---------------------------------------------------------------------------
// Helpers: mma.sync / ldmatrix / cp.async (valid on compute_103 PTX)
// ---------------------------------------------------------------------------
__device__ __forceinline__ uint32_t smem_to_u32(const void* p) {
    uint32_t a;
    asm("{ .reg .u64 t; cvta.to.shared.u64 t, %1; cvt.u32.u64 %0, t; }"
        : "=r"(a) : "l"(p));
    return a;
}

__device__ __forceinline__ void ldsm_x4(uint32_t* r, uint32_t addr) {
    asm volatile("ldmatrix.sync.aligned.m8n8.x4.shared.b16 {%0,%1,%2,%3}, [%4];"
        : "=r"(r[0]), "=r"(r[1]), "=r"(r[2]), "=r"(r[3]) : "r"(addr));
}

__device__ __forceinline__ void mma_bf16(float* c, const uint32_t* a, const uint32_t* b) {
    asm volatile(
        "mma.sync.aligned.m16n8k16.row.col.f32.bf16.bf16.f32 "
        "{%0,%1,%2,%3}, {%4,%5,%6,%7}, {%8,%9}, {%0,%1,%2,%3};"
        : "+f"(c[0]), "+f"(c[1]), "+f"(c[2]), "+f"(c[3])
        : "r"(a[0]), "r"(a[1]), "r"(a[2]), "r"(a[3]),
          "r"(b[0]), "r"(b[1]));
}

#define CP_ASYNC16(dst, src) \
    asm volatile("cp.async.cg.shared.global [%0], [%1], 16;" \
        :: "r"(dst), "l"(src) : "memory")
#define CP_COMMIT() asm volatile("cp.async.commit_group;" ::: "memory")
#define CP_WAIT1()  asm volatile("cp.async.wait_group 1;" ::: "memory")

// FMA-pipe exp2 (avoids the MUFU ceiling). x <= 0 expected.
__device__ __forceinline__ float exp2p(float x) {
    x = fmaxf(x, -28.0f);
    float n = floorf(x);
    float f = x - n;
    float p = 1.54035304e-4f;
    p = fmaf(p, f, 1.33335581e-3f);
    p = fmaf(p, f, 9.61812911e-3f);
    p = fmaf(p, f, 5.55041087e-2f);
    p = fmaf(p, f, 2.40226507e-1f);
    p = fmaf(p, f, 6.93147181e-1f);
    p = fmaf(p, f, 1.0f);
    return __int_as_float(__float_as_int(p) + (((int)n) << 23));
}

__device__ __forceinline__ void split_bf16(float v, __nv_bfloat16& h, __nv_bfloat16& l) {
    h = __float2bfloat16(v);
    l = __float2bfloat16(v - __bfloat162float(h));
}

// ---------------------------------------------------------------------------
// One-shot converter: x -> g_xh/g_xl ; Wq,Wk,Wv,Wo -> g_wh/g_wl (stacked rows)
// ---------------------------------------------------------------------------
__global__ void __launch_bounds__(256)
convert_all_kernel(const float* __restrict__ x,
                   const float* __restrict__ Wq, const float* __restrict__ Wk,
                   const float* __restrict__ Wv, const float* __restrict__ Wo)
{
    const int tid = threadIdx.x;
    const int blk = blockIdx.x;

    const float* src;
    __nv_bfloat16 *hi, *lo;
    size_t sbase, dbase;
    if (blk < 4096) {
        src = x; hi = g_xh; lo = g_xl;
        sbase = (size_t)blk * 1024; dbase = sbase;
    } else {
        const int t = blk - 4096;
        const int w = t >> 10;
        const int lb = t & 1023;
        src = (w == 0) ? Wq : (w == 1) ? Wk : (w == 2) ? Wv : Wo;
        hi = g_wh; lo = g_wl;
        sbase = (size_t)lb * 1024;
        dbase = (size_t)w * (D_ * D_) + sbase;
    }

    const int i = tid * 4;
    float4 v = *(const float4*)(src + sbase + i);
    float f[4] = {v.x, v.y, v.z, v.w};
    __nv_bfloat16 h[4], l[4];
#pragma unroll
    for (int k = 0; k < 4; k++) split_bf16(f[k], h[k], l[k]);
    __nv_bfloat162* ph = (__nv_bfloat162*)(hi + dbase + i);
    __nv_bfloat162* pl = (__nv_bfloat162*)(lo + dbase + i);
    ph[0] = __halves2bfloat162(h[0], h[1]);
    ph[1] = __halves2bfloat162(h[2], h[3]);
    pl[0] = __halves2bfloat162(l[0], l[1]);
    pl[1] = __halves2bfloat162(l[2], l[3]);
}

// ---------------------------------------------------------------------------
// bf16x3 GEMM via mma.sync: C[M,N] = A @ W^T + bias.
// 2-stage cp.async pipeline, 2 CTAs/SM (smem 81920, regs capped at 128).
// dst == nullptr: merged QKV (N = 3072, sel = bn>>10). dst != nullptr: O proj.
// ---------------------------------------------------------------------------
constexpr int KPAD    = 40;
constexpr int TILE_B  = 128 * KPAD * 2;        // 10240 B
constexpr int STAGE_B = 4 * TILE_B;            // 40960 B
constexpr int GEMM_SMEM = 2 * STAGE_B;         // 81920 B

__global__ void __launch_bounds__(256, 2)
gemm_mma_kernel(const float* __restrict__ b0,
                const float* __restrict__ b1,
                const float* __restrict__ b2,
                float* __restrict__ dst,
                int wrow0)
{
    extern __shared__ __align__(1024) char smem[];
    const uint32_t sb = smem_to_u32(smem);
    const int tid = threadIdx.x;
    const int wid = tid >> 5;
    const int lid = tid & 31;
    const int wm  = wid & 3;
    const int wn  = wid >> 2;
    const int bm  = blockIdx.y * 128;
    const int bn  = blockIdx.x * 128;
    const int sel = bn >> 10;                  // 0/1/2 for QKV; 0 for O

    const float* bias = dst ? b0 : (sel == 0 ? b0 : sel == 1 ? b1 : b2);

    const int r4 = tid >> 2;
    const int s4 = tid & 3;

    auto issue_stage = [&](int st) {
        const int k0 = st * 32;
        const uint32_t sbase = sb + (st & 1) * STAGE_B;
#pragma unroll
        for (int j = 0; j < 2; j++) {
            const int r = r4 + j * 64;
            const uint32_t doff = (uint32_t)(r * KPAD + s4 * 8) * 2;
            const size_t aoff = (size_t)(bm + r) * D_ + k0 + s4 * 8;
            const size_t boff = (size_t)(wrow0 + bn + r) * D_ + k0 + s4 * 8;
            CP_ASYNC16(sbase + 0 * TILE_B + doff, g_xh + aoff);
            CP_ASYNC16(sbase + 1 * TILE_B + doff, g_xl + aoff);
            CP_ASYNC16(sbase + 2 * TILE_B + doff, g_wh + boff);
            CP_ASYNC16(sbase + 3 * TILE_B + doff, g_wl + boff);
        }
    };

    float c[2][8][4];
#pragma unroll
    for (int i = 0; i < 2; i++)
#pragma unroll
        for (int j = 0; j < 8; j++)
#pragma unroll
            for (int k = 0; k < 4; k++) c[i][j][k] = 0.f;

    const uint32_t a_r  = lid & 15;
    const uint32_t a_c8 = (lid >> 4) * 8;
    const uint32_t b_r  = ((lid >> 4) * 8) + (lid & 7);
    const uint32_t b_c8 = ((lid >> 3) & 1) * 8;

    issue_stage(0); CP_COMMIT();
    issue_stage(1); CP_COMMIT();

    const int NCH = D_ / 32;
    for (int ch = 0; ch < NCH; ch++) {
        CP_WAIT1();
        __syncthreads();

        const uint32_t sA_h = sb + (ch & 1) * STAGE_B;
        const uint32_t sA_l = sA_h + TILE_B;
        const uint32_t sB_h = sA_h + 2 * TILE_B;
        const uint32_t sB_l = sA_h + 3 * TILE_B;

#pragma unroll
        for (int kk = 0; kk < 2; kk++) {
            uint32_t ah[2][4], al[2][4];
#pragma unroll
            for (int mt = 0; mt < 2; mt++) {
                const uint32_t aoff =
                    ((wm * 32 + mt * 16 + a_r) * KPAD + kk * 16 + a_c8) * 2;
                ldsm_x4(ah[mt], sA_h + aoff);
                ldsm_x4(al[mt], sA_l + aoff);
            }
            uint32_t bh[4][4], bl[4][4];
#pragma unroll
            for (int np = 0; np < 4; np++) {
                const uint32_t boff =
                    ((wn * 64 + np * 16 + b_r) * KPAD + kk * 16 + b_c8) * 2;
                ldsm_x4(bh[np], sB_h + boff);
                ldsm_x4(bl[np], sB_l + boff);
            }
#pragma unroll
            for (int mt = 0; mt < 2; mt++)
#pragma unroll
                for (int np = 0; np < 4; np++) {
                    mma_bf16(c[mt][2*np],   ah[mt], bh[np]);
                    mma_bf16(c[mt][2*np+1], ah[mt], bh[np] + 2);
                }
#pragma unroll
            for (int mt = 0; mt < 2; mt++)
#pragma unroll
                for (int np = 0; np < 4; np++) {
                    mma_bf16(c[mt][2*np],   ah[mt], bl[np]);
                    mma_bf16(c[mt][2*np+1], ah[mt], bl[np] + 2);
                }
#pragma unroll
            for (int mt = 0; mt < 2; mt++)
#pragma unroll
                for (int np = 0; np < 4; np++) {
                    mma_bf16(c[mt][2*np],   al[mt], bh[np]);
                    mma_bf16(c[mt][2*np+1], al[mt], bh[np] + 2);
                }
        }

        __syncthreads();
        if (ch + 2 < NCH) issue_stage(ch + 2);
        CP_COMMIT();
    }

    // ---- epilogue ------------------------------------------------------
#pragma unroll
    for (int mt = 0; mt < 2; mt++) {
#pragma unroll
        for (int nt = 0; nt < 8; nt++) {
            const int row0 = bm + wm * 32 + mt * 16 + (lid >> 2);
            const int row1 = row0 + 8;
            const int col  = bn + wn * 64 + nt * 8 + (lid & 3) * 2;
            const int colw = col & 1023;
            const float bx = __ldg(bias + colw);
            const float by = __ldg(bias + colw + 1);
            float v0 = c[mt][nt][0] + bx, v1 = c[mt][nt][1] + by;
            float v2 = c[mt][nt][2] + bx, v3 = c[mt][nt][3] + by;

            if (dst) {
                *(float2*)(dst + (size_t)row0 * D_ + col) = make_float2(v0, v1);
                *(float2*)(dst + (size_t)row1 * D_ + col) = make_float2(v2, v3);
            } else {
                const int h  = colw >> 6;
                const int hd = colw & 63;
                const int bb0 = row0 >> 11, ss0 = row0 & (S_ - 1);
                const int bb1 = row1 >> 11, ss1 = row1 & (S_ - 1);
                __nv_bfloat16 h0,l0,h1,l1,h2,l2,h3,l3;
                split_bf16(v0,h0,l0); split_bf16(v1,h1,l1);
                split_bf16(v2,h2,l2); split_bf16(v3,h3,l3);
                if (sel == 2) {
                    size_t base0 = (((size_t)(bb0 * H_ + h) * HD_) + hd) * S_;
                    size_t base1 = (((size_t)(bb1 * H_ + h) * HD_) + hd) * S_;
                    g_Vth[base0 + ss0]      = h0; g_Vtl[base0 + ss0]      = l0;
                    g_Vth[base0 + S_ + ss0] = h1; g_Vtl[base0 + S_ + ss0] = l1;
                    g_Vth[base1 + ss1]      = h2; g_Vtl[base1 + ss1]      = l2;
                    g_Vth[base1 + S_ + ss1] = h3; g_Vtl[base1 + S_ + ss1] = l3;
                } else {
                    __nv_bfloat16* dh = (sel == 0) ? g_Qh : g_Kh;
                    __nv_bfloat16* dl = (sel == 0) ? g_Ql : g_Kl;
                    size_t i0 = (((size_t)(bb0 * H_ + h) * S_) + ss0) * HD_ + hd;
                    size_t i1 = (((size_t)(bb1 * H_ + h) * S_) + ss1) * HD_ + hd;
                    *(__nv_bfloat162*)(dh + i0) = __halves2bfloat162(h0, h1);
                    *(__nv_bfloat162*)(dl + i0) = __halves2bfloat162(l0, l1);
                    *(__nv_bfloat162*)(dh + i1) = __halves2bfloat162(h2, h3);
                    *(__nv_bfloat162*)(dl + i1) = __halves2bfloat162(l2, l3);
                }
            }
        }
    }
}

// ---------------------------------------------------------------------------
// Flash attention via mma.sync bf16x3 + FMA-pipe exp2.
// Q fragments loaded DIRECTLY from gmem (no Q smem) -> smem 73728, 2 CTAs/SM.
// Grid (S/128, B*H), 256 threads (8 warps x 16 query rows). Bc = 64.
// ---------------------------------------------------------------------------
constexpr int FKP = 72;
constexpr int FKV_B   = 64 * FKP * 2;           // 9216 B
constexpr int FSTAGE_B = 4 * FKV_B;             // 36864 B
constexpr int FLASH_SMEM = 2 * FSTAGE_B;        // 73728 B
constexpr float SCL2 = 0.18033688f;             // 0.125 * log2(e)

__global__ void __launch_bounds__(256, 2)
flash_mma_kernel()
{
    extern __shared__ __align__(1024) char fsm[];
    const uint32_t sb = smem_to_u32(fsm);
    const int tid = threadIdx.x;
    const int wid = tid >> 5;
    const int lid = tid & 31;
    const int bh  = blockIdx.y;
    const int q0  = blockIdx.x * 128;

    const size_t qk_base = (size_t)bh * S_ * HD_;
    const size_t vt_base = (size_t)bh * HD_ * S_;
    const __nv_bfloat16* Qh = g_Qh + qk_base;
    const __nv_bfloat16* Ql = g_Ql + qk_base;
    const __nv_bfloat16* Kh = g_Kh + qk_base;
    const __nv_bfloat16* Kl = g_Kl + qk_base;
    const __nv_bfloat16* Vh = g_Vth + vt_base;
    const __nv_bfloat16* Vl = g_Vtl + vt_base;

    auto issue_kv = [&](int t) {
        const int k0 = t * 64;
        const uint32_t st = sb + (t & 1) * FSTAGE_B;
        const int row = tid >> 2;
        const int c0  = (tid & 3) * 16;
        const uint32_t doff = (uint32_t)(row * FKP + c0) * 2;
        const size_t koff = (size_t)(k0 + row) * HD_ + c0;
        const size_t voff = (size_t)row * S_ + k0 + c0;
#pragma unroll
        for (int j = 0; j < 2; j++) {
            CP_ASYNC16(st + 0 * FKV_B + doff + j * 16, Kh + koff + j * 8);
            CP_ASYNC16(st + 1 * FKV_B + doff + j * 16, Kl + koff + j * 8);
            CP_ASYNC16(st + 2 * FKV_B + doff + j * 16, Vh + voff + j * 8);
            CP_ASYNC16(st + 3 * FKV_B + doff + j * 16, Vl + voff + j * 8);
        }
    };

    issue_kv(0); CP_COMMIT();
    issue_kv(1); CP_COMMIT();

    // Q fragments straight from gmem (fragment layout: reg r of lane ->
    // A[g(+8)][2t(+8)], g = lid>>2, t = lid&3). Overlaps the cp.async fills.
    uint32_t qfh[4][4], qfl[4][4];
    {
        const int g  = lid >> 2;
        const int tq = lid & 3;
        const int row0 = q0 + wid * 16 + g;
#pragma unroll
        for (int kk = 0; kk < 4; kk++) {
            const int c0 = kk * 16 + 2 * tq;
            const size_t i00 = (size_t)row0 * HD_ + c0;
            const size_t i10 = i00 + 8 * HD_;
            qfh[kk][0] = *(const uint32_t*)(Qh + i00);
            qfh[kk][1] = *(const uint32_t*)(Qh + i10);
            qfh[kk][2] = *(const uint32_t*)(Qh + i00 + 8);
            qfh[kk][3] = *(const uint32_t*)(Qh + i10 + 8);
            qfl[kk][0] = *(const uint32_t*)(Ql + i00);
            qfl[kk][1] = *(const uint32_t*)(Ql + i10);
            qfl[kk][2] = *(const uint32_t*)(Ql + i00 + 8);
            qfl[kk][3] = *(const uint32_t*)(Ql + i10 + 8);
        }
    }

    const uint32_t b_r  = ((lid >> 4) * 8) + (lid & 7);
    const uint32_t b_c8 = ((lid >> 3) & 1) * 8;

    float o[8][4];
#pragma unroll
    for (int i = 0; i < 8; i++)
#pragma unroll
        for (int j = 0; j < 4; j++) o[i][j] = 0.f;
    float m0 = -1e30f, m1 = -1e30f, l0 = 0.f, l1 = 0.f;

    const int NKV = S_ / 64;
    for (int t = 0; t < NKV; t++) {
        CP_WAIT1();
        __syncthreads();

        const uint32_t st  = sb + (t & 1) * FSTAGE_B;
        const uint32_t sKh = st, sKl = st + FKV_B;
        const uint32_t sVh = st + 2 * FKV_B, sVl = st + 3 * FKV_B;

        // ---- S = Q K^T (term-major) --------------------------------------
        float c[8][4];
#pragma unroll
        for (int i = 0; i < 8; i++)
#pragma unroll
            for (int j = 0; j < 4; j++) c[i][j] = 0.f;

#pragma unroll
        for (int kk = 0; kk < 4; kk++) {
            uint32_t kfh[4][4], kfl[4][4];
#pragma unroll
            for (int np = 0; np < 4; np++) {
                const uint32_t boff = ((np * 16 + b_r) * FKP + kk * 16 + b_c8) * 2;
                ldsm_x4(kfh[np], sKh + boff);
                ldsm_x4(kfl[np], sKl + boff);
            }
#pragma unroll
            for (int np = 0; np < 4; np++) {
                mma_bf16(c[2*np],   qfh[kk], kfh[np]);
                mma_bf16(c[2*np+1], qfh[kk], kfh[np] + 2);
            }
#pragma unroll
            for (int np = 0; np < 4; np++) {
                mma_bf16(c[2*np],   qfh[kk], kfl[np]);
                mma_bf16(c[2*np+1], qfh[kk], kfl[np] + 2);
            }
#pragma unroll
            for (int np = 0; np < 4; np++) {
                mma_bf16(c[2*np],   qfl[kk], kfh[np]);
                mma_bf16(c[2*np+1], qfl[kk], kfh[np] + 2);
            }
        }

        // ---- online softmax ----------------------------------------------
        float mx0 = -1e30f, mx1 = -1e30f;
#pragma unroll
        for (int nt = 0; nt < 8; nt++) {
            mx0 = fmaxf(mx0, fmaxf(c[nt][0], c[nt][1]));
            mx1 = fmaxf(mx1, fmaxf(c[nt][2], c[nt][3]));
        }
        mx0 = fmaxf(mx0, __shfl_xor_sync(0xffffffffu, mx0, 1));
        mx0 = fmaxf(mx0, __shfl_xor_sync(0xffffffffu, mx0, 2));
        mx1 = fmaxf(mx1, __shfl_xor_sync(0xffffffffu, mx1, 1));
        mx1 = fmaxf(mx1, __shfl_xor_sync(0xffffffffu, mx1, 2));

        const float mn0 = fmaxf(m0, mx0), mn1 = fmaxf(m1, mx1);
        const float al0 = exp2p((m0 - mn0) * SCL2);
        const float al1 = exp2p((m1 - mn1) * SCL2);
        m0 = mn0; m1 = mn1;
        const float mb0 = mn0 * SCL2, mb1 = mn1 * SCL2;

        float s0 = 0.f, s1 = 0.f;
#pragma unroll
        for (int nt = 0; nt < 8; nt++) {
            c[nt][0] = exp2p(fmaf(c[nt][0], SCL2, -mb0));
            c[nt][1] = exp2p(fmaf(c[nt][1], SCL2, -mb0));
            c[nt][2] = exp2p(fmaf(c[nt][2], SCL2, -mb1));
            c[nt][3] = exp2p(fmaf(c[nt][3], SCL2, -mb1));
            s0 += c[nt][0] + c[nt][1];
            s1 += c[nt][2] + c[nt][3];
        }
        s0 += __shfl_xor_sync(0xffffffffu, s0, 1);
        s0 += __shfl_xor_sync(0xffffffffu, s0, 2);
        s1 += __shfl_xor_sync(0xffffffffu, s1, 1);
        s1 += __shfl_xor_sync(0xffffffffu, s1, 2);
        l0 = l0 * al0 + s0;
        l1 = l1 * al1 + s1;

#pragma unroll
        for (int nt = 0; nt < 8; nt++) {
            o[nt][0] *= al0; o[nt][1] *= al0;
            o[nt][2] *= al1; o[nt][3] *= al1;
        }

        // ---- pack P into A-fragments (hi/lo) ------------------------------
        uint32_t pfh[4][4], pfl[4][4];
#pragma unroll
        for (int kk2 = 0; kk2 < 4; kk2++) {
            const int n0 = 2 * kk2, n1 = 2 * kk2 + 1;
            float ph[8], pl[8];
            float src[8] = {c[n0][0], c[n0][1], c[n0][2], c[n0][3],
                            c[n1][0], c[n1][1], c[n1][2], c[n1][3]};
#pragma unroll
            for (int e = 0; e < 8; e++) {
                __nv_bfloat16 hb = __float2bfloat16(src[e]);
                ph[e] = __bfloat162float(hb);
                pl[e] = src[e] - ph[e];
            }
            __nv_bfloat162 t0, t1;
#pragma unroll
            for (int q = 0; q < 4; q++) {
                t0 = __floats2bfloat162_rn(ph[2*q], ph[2*q+1]);
                t1 = __floats2bfloat162_rn(pl[2*q], pl[2*q+1]);
                pfh[kk2][q] = *(uint32_t*)&t0;
                pfl[kk2][q] = *(uint32_t*)&t1;
            }
        }

        // ---- O += P V (term-major) ----------------------------------------
#pragma unroll
        for (int kk2 = 0; kk2 < 4; kk2++) {
            uint32_t vfh[4][4], vfl[4][4];
#pragma unroll
            for (int np = 0; np < 4; np++) {
                const uint32_t boff = ((np * 16 + b_r) * FKP + kk2 * 16 + b_c8) * 2;
                ldsm_x4(vfh[np], sVh + boff);
                ldsm_x4(vfl[np], sVl + boff);
            }
#pragma unroll
            for (int np = 0; np < 4; np++) {
                mma_bf16(o[2*np],   pfh[kk2], vfh[np]);
                mma_bf16(o[2*np+1], pfh[kk2], vfh[np] + 2);
            }
#pragma unroll
            for (int np = 0; np < 4; np++) {
                mma_bf16(o[2*np],   pfh[kk2], vfl[np]);
                mma_bf16(o[2*np+1], pfh[kk2], vfl[np] + 2);
            }
#pragma unroll
            for (int np = 0; np < 4; np++) {
                mma_bf16(o[2*np],   pfl[kk2], vfh[np]);
                mma_bf16(o[2*np+1], pfl[kk2], vfh[np] + 2);
            }
        }

        __syncthreads();
        if (t + 2 < NKV) issue_kv(t + 2);
        CP_COMMIT();
    }

    // ---- epilogue: normalize, write bf16 hi/lo into final-GEMM staging ----
    const int b = bh >> 4;
    const int h = bh & 15;
    const float li0 = 1.f / l0;
    const float li1 = 1.f / l1;
    const int r0 = q0 + wid * 16 + (lid >> 2);
    const int r1 = r0 + 8;
    const size_t g0 = ((size_t)(b * S_ + r0)) * D_ + h * 64;
    const size_t g1 = ((size_t)(b * S_ + r1)) * D_ + h * 64;

#pragma unroll
    for (int nt = 0; nt < 8; nt++) {
        const int col = nt * 8 + (lid & 3) * 2;
        float v0 = o[nt][0] * li0, v1 = o[nt][1] * li0;
        float v2 = o[nt][2] * li1, v3 = o[nt][3] * li1;
        __nv_bfloat16 h0,lo0,h1,lo1,h2,lo2,h3,lo3;
        split_bf16(v0,h0,lo0); split_bf16(v1,h1,lo1);
        split_bf16(v2,h2,lo2); split_bf16(v3,h3,lo3);
        *(__nv_bfloat162*)(g_xh + g0 + col) = __halves2bfloat162(h0, h1);
        *(__nv_bfloat162*)(g_xl + g0 + col) = __halves2bfloat162(lo0, lo1);
        *(__nv_bfloat162*)(g_xh + g1 + col) = __halves2bfloat162(h2, h3);
        *(__nv_bfloat162*)(g_xl + g1 + col) = __halves2bfloat162(lo2, lo3);
    }
}

// ---------------------------------------------------------------------------
// Entry point
// ---------------------------------------------------------------------------
extern "C" void kernel_launch(void* const* d_in, const int* in_sizes, int n_in,
                              void* d_out, int out_size)
{
    const float* x  = (const float*)d_in[0];
    const float* Wq = (const float*)d_in[1];
    const float* bq = (const float*)d_in[2];
    const float* Wk = (const float*)d_in[3];
    const float* bk = (const float*)d_in[4];
    const float* Wv = (const float*)d_in[5];
    const float* bv = (const float*)d_in[6];
    const float* Wo = (const float*)d_in[7];
    const float* bo = (const float*)d_in[8];
    float* out = (float*)d_out;

    cudaFuncSetAttribute(gemm_mma_kernel,
                         cudaFuncAttributeMaxDynamicSharedMemorySize, GEMM_SMEM);
    cudaFuncSetAttribute(flash_mma_kernel,
                         cudaFuncAttributeMaxDynamicSharedMemorySize, FLASH_SMEM);

    // 1) convert x + all 4 weights (bf16 hi/lo) in one launch
    convert_all_kernel<<<8192, 256>>>(x, Wq, Wk, Wv, Wo);

    // 2) merged QKV projection: N = 3072
    gemm_mma_kernel<<<dim3(24, 32), 256, GEMM_SMEM>>>(bq, bk, bv, nullptr, 0);

    // 3) flash attention (writes bf16 hi/lo straight into GEMM A-staging)
    flash_mma_kernel<<<dim3(S_ / 128, B_ * H_), 256, FLASH_SMEM>>>();

    // 4) output projection (weight rows 3072..4095)
    gemm_mma_kernel<<<dim3(8, 32), 256, GEMM_SMEM>>>(bo, bo, bo, out, 3072);
}